// round 8
// baseline (speedup 1.0000x reference)
#include <cuda_runtime.h>
#include <cuda_bf16.h>
#include <cstdint>

#define BS 4
#define SEQ 4096
#define DK 128
#define SCALE 0.08838834764831843f   // 1/sqrt(128)
#define NT 32                        // 4096/128 tiles
#define NS2 8                        // split-K for output GEMM
#define SEG 4608                     // blob segment = 128 rows x 72 bf16 = 18432 B
#define TS  (4*SEG)                  // tile blob = [hi c0][hi c1][lo c0][lo c1]

// Pipelined stage: 4 parts x (128 rows x 80B) = 40960 B; two stages = 81920 B
// Row stride 80 = multiple of 16 (cp.async alignment) and conflict-free for ldsm.
#define RS2 80
#define PART_BYTES 10240
#define P_AH 0
#define P_AL 10240
#define P_BH 20480
#define P_BL 30720
#define STAGE_BYTES 40960
#define SMEM_BYTES 81920

// Blobs: exact padded images -> GEMM loads are raw async copies.
__device__ uint32_t g_Q[(size_t)BS*NT*TS];
__device__ uint32_t g_K[(size_t)BS*NT*TS];
__device__ uint32_t g_W[(size_t)BS*NT*TS];      // coef*V transposed [d][k]
__device__ uint32_t g_P[(size_t)BS*NT*NT*TS];   // ~300 MB
__device__ float g_colsum[BS*SEQ];

// ------------------------------------------------------------------ helpers
__device__ __forceinline__ uint32_t smem_u32(const void* p) {
    uint32_t a;
    asm("{ .reg .u64 t; cvta.to.shared.u64 t, %1; cvt.u32.u64 %0, t; }" : "=r"(a) : "l"(p));
    return a;
}
__device__ __forceinline__ void ldsm4(uint32_t* r, uint32_t addr) {
    asm volatile("ldmatrix.sync.aligned.m8n8.x4.shared.b16 {%0,%1,%2,%3}, [%4];"
                 : "=r"(r[0]), "=r"(r[1]), "=r"(r[2]), "=r"(r[3]) : "r"(addr));
}
__device__ __forceinline__ void mma16816(float* c, const uint32_t* a, uint32_t b0, uint32_t b1) {
    asm volatile("mma.sync.aligned.m16n8k16.row.col.f32.bf16.bf16.f32 "
                 "{%0,%1,%2,%3}, {%4,%5,%6,%7}, {%8,%9}, {%0,%1,%2,%3};"
                 : "+f"(c[0]), "+f"(c[1]), "+f"(c[2]), "+f"(c[3])
                 : "r"(a[0]), "r"(a[1]), "r"(a[2]), "r"(a[3]), "r"(b0), "r"(b1));
}
__device__ __forceinline__ void bsplit2(float x, float y, uint32_t& h, uint32_t& l) {
    __nv_bfloat16 hx = __float2bfloat16(x), hy = __float2bfloat16(y);
    __nv_bfloat16 lx = __float2bfloat16(x - __bfloat162float(hx));
    __nv_bfloat16 ly = __float2bfloat16(y - __bfloat162float(hy));
    h = (uint32_t)__bfloat16_as_ushort(hx) | ((uint32_t)__bfloat16_as_ushort(hy) << 16);
    l = (uint32_t)__bfloat16_as_ushort(lx) | ((uint32_t)__bfloat16_as_ushort(ly) << 16);
}
__device__ __forceinline__ void cp16(uint32_t sdst, const void* gsrc) {
    asm volatile("cp.async.cg.shared.global [%0], [%1], 16;" :: "r"(sdst), "l"(gsrc) : "memory");
}
__device__ __forceinline__ void cp_commit() { asm volatile("cp.async.commit_group;" ::: "memory"); }
__device__ __forceinline__ void cp_wait0() { asm volatile("cp.async.wait_group 0;" ::: "memory"); }
__device__ __forceinline__ void cp_wait1() { asm volatile("cp.async.wait_group 1;" ::: "memory"); }

// Issue one 32-k sub-chunk (4 parts x 128 rows x 64B) from blobs into a stage.
// ch = 64-k chunk (0/1), h = 32-k half (0/1).
__device__ __forceinline__ void issue_sub(uint32_t stage, const uint32_t* Ab, const uint32_t* Bb,
                                          int ch, int h, int tid) {
    const uint32_t* segs[4] = { Ab + ch * SEG, Ab + (2 + ch) * SEG,
                                Bb + ch * SEG, Bb + (2 + ch) * SEG };
    #pragma unroll
    for (int i = 0; i < 8; i++) {
        int t = tid + i * 256;
        int part = t >> 9;           // uniform per i
        int w = t & 511, row = w >> 2, q = w & 3;
        const char* src = (const char*)segs[part] + row * 144 + h * 64 + q * 16;
        cp16(stage + part * PART_BYTES + row * RS2 + q * 16, src);
    }
    cp_commit();
}

// ---------------------------------------------------------------------------
// 3-pass bf16-split sub-chunk GEMM: acc += A~ * B~^T over 32 k (stage @sbase).
// Warp tile 64x32 (warps 2x4). acc[mi][ng][4].
// ---------------------------------------------------------------------------
__device__ __forceinline__ void mma_sub(uint32_t sbase, float acc[4][4][4],
                                        int warp_m, int warp_n, int lane) {
    int rIn  = (lane & 7) + ((lane >> 3) & 1) * 8;
    int kOff = (lane >> 4) * 16;
    int aRow0 = warp_m * 64 + rIn;
    int bRow0 = warp_n * 32 + rIn;

    // pass 1+2: A_hi x (B_hi, B_lo)
    #pragma unroll
    for (int s = 0; s < 2; s++) {
        uint32_t a[4][4], bh[2][4], bl[2][4];
        #pragma unroll
        for (int mi = 0; mi < 4; mi++)
            ldsm4(a[mi], sbase + P_AH + (aRow0 + mi * 16) * RS2 + kOff + s * 32);
        #pragma unroll
        for (int nj = 0; nj < 2; nj++) {
            ldsm4(bh[nj], sbase + P_BH + (bRow0 + nj * 16) * RS2 + kOff + s * 32);
            ldsm4(bl[nj], sbase + P_BL + (bRow0 + nj * 16) * RS2 + kOff + s * 32);
        }
        #pragma unroll
        for (int mi = 0; mi < 4; mi++)
            #pragma unroll
            for (int ng = 0; ng < 4; ng++) {
                int nj = ng >> 1, g = ng & 1;
                mma16816(acc[mi][ng], a[mi], bh[nj][g], bh[nj][g + 2]);
                mma16816(acc[mi][ng], a[mi], bl[nj][g], bl[nj][g + 2]);
            }
    }
    // pass 3: A_lo x B_hi
    #pragma unroll
    for (int s = 0; s < 2; s++) {
        uint32_t a[4][4], bh[2][4];
        #pragma unroll
        for (int mi = 0; mi < 4; mi++)
            ldsm4(a[mi], sbase + P_AL + (aRow0 + mi * 16) * RS2 + kOff + s * 32);
        #pragma unroll
        for (int nj = 0; nj < 2; nj++)
            ldsm4(bh[nj], sbase + P_BH + (bRow0 + nj * 16) * RS2 + kOff + s * 32);
        #pragma unroll
        for (int mi = 0; mi < 4; mi++)
            #pragma unroll
            for (int ng = 0; ng < 4; ng++) {
                int nj = ng >> 1, g = ng & 1;
                mma16816(acc[mi][ng], a[mi], bh[nj][g], bh[nj][g + 2]);
            }
    }
}

// ---------------------------------------------------------------- tiny kernels
__global__ void zero_kernel() {
    int i = blockIdx.x * blockDim.x + threadIdx.x;
    if (i < BS * SEQ) g_colsum[i] = 0.f;
}
__global__ void recip_kernel() {
    int i = blockIdx.x * blockDim.x + threadIdx.x;
    if (i < BS * SEQ) g_colsum[i] = 1.0f / g_colsum[i];
}
__global__ void zero_out_kernel(float* __restrict__ O) {
    size_t i4 = (size_t)blockIdx.x * blockDim.x + threadIdx.x;
    if (i4 < (size_t)BS * SEQ * DK / 4)
        ((float4*)O)[i4] = make_float4(0.f, 0.f, 0.f, 0.f);
}

// ---------------------------------------------------------------------------
// Q/K f32 -> bf16 hi/lo padded blobs
// ---------------------------------------------------------------------------
__global__ __launch_bounds__(256)
void convert_qk(const float* __restrict__ Q, const float* __restrict__ K) {
    int tile = blockIdx.x, which = blockIdx.y, b = blockIdx.z;
    const float* src = (which ? K : Q) + ((size_t)b * SEQ + tile * 128) * DK;
    uint32_t* dst = (which ? g_K : g_Q) + (size_t)(b * NT + tile) * TS;

    for (int i = threadIdx.x; i < 2 * SEG; i += 256) {
        int ch = i / SEG, j = i % SEG;
        int row = j / 36, cp = j % 36;
        uint32_t h = 0, l = 0;
        if (cp < 32) {
            float2 v = *(const float2*)&src[row * DK + ch * 64 + cp * 2];
            bsplit2(v.x, v.y, h, l);
        }
        dst[ch * SEG + j] = h;
        dst[(2 + ch) * SEG + j] = l;
    }
}

// ---------------------------------------------------------------------------
// V f32 -> W blob: W[d][k] = coef_k * V[k][d], bf16 hi/lo, padded image.
// ---------------------------------------------------------------------------
__global__ __launch_bounds__(256)
void convert_v(const float* __restrict__ V) {
    int kb = blockIdx.x, b = blockIdx.y;
    const float* Vb = V + (size_t)b * SEQ * DK;
    const float* Cb = g_colsum + b * SEQ;
    uint32_t* dst = g_W + (size_t)(b * NT + kb) * TS;

    for (int i = threadIdx.x; i < 2 * SEG; i += 256) {
        int ch = i / SEG, j = i % SEG;
        int d = j / 36, kp = j % 36;
        uint32_t h = 0, l = 0;
        if (kp < 32) {
            int k = kb * 128 + ch * 64 + 2 * kp;
            float v0 = Vb[(size_t)k * DK + d]       * Cb[k];
            float v1 = Vb[(size_t)(k + 1) * DK + d] * Cb[k + 1];
            bsplit2(v0, v1, h, l);
        }
        dst[ch * SEG + j] = h;
        dst[(2 + ch) * SEG + j] = l;
    }
}

// ---------------------------------------------------------------------------
// Kernel 1: S = Q.K^T, pipelined 32-k sub-chunks; epilogue exp -> P blob,
// colsums via register shuffle reduction.
// ---------------------------------------------------------------------------
__global__ __launch_bounds__(256, 2)
void scores_hmma() {
    extern __shared__ char smem[];
    uint32_t sb = smem_u32(smem);
    int tid = threadIdx.x, lane = tid & 31, wid = tid >> 5;
    int warp_m = wid >> 2, warp_n = wid & 3;
    int kt = blockIdx.x, qt = blockIdx.y, b = blockIdx.z;

    const uint32_t* Qb = g_Q + (size_t)(b * NT + qt) * TS;
    const uint32_t* Kb = g_K + (size_t)(b * NT + kt) * TS;

    float acc[4][4][4];
    #pragma unroll
    for (int i = 0; i < 4; i++)
        #pragma unroll
        for (int j = 0; j < 4; j++)
            #pragma unroll
            for (int c = 0; c < 4; c++) acc[i][j][c] = 0.f;

    issue_sub(sb, Qb, Kb, 0, 0, tid);
    issue_sub(sb + STAGE_BYTES, Qb, Kb, 0, 1, tid);

    for (int s = 0; s < 4; s++) {
        if (s < 3) cp_wait1(); else cp_wait0();
        __syncthreads();
        mma_sub(sb + (s & 1) * STAGE_BYTES, acc, warp_m, warp_n, lane);
        __syncthreads();
        if (s + 2 < 4)
            issue_sub(sb + (s & 1) * STAGE_BYTES, Qb, Kb, (s + 2) >> 1, (s + 2) & 1, tid);
    }

    // Epilogue: exp -> bf16 hi/lo staged as blob image; colsum partials in regs.
    float cs[4][2];
    #pragma unroll
    for (int ng = 0; ng < 4; ng++) { cs[ng][0] = 0.f; cs[ng][1] = 0.f; }

    #pragma unroll
    for (int mi = 0; mi < 4; mi++)
        #pragma unroll
        for (int ng = 0; ng < 4; ng++) {
            int R = warp_m * 64 + mi * 16 + (lane >> 2);
            int C = warp_n * 32 + ng * 8 + 2 * (lane & 3);
            int ch = C >> 6, cc = C & 63;
            #pragma unroll
            for (int rr = 0; rr < 2; rr++) {
                float p0 = __expf(acc[mi][ng][rr * 2]     * SCALE);
                float p1 = __expf(acc[mi][ng][rr * 2 + 1] * SCALE);
                cs[ng][0] += p0;
                cs[ng][1] += p1;
                uint32_t h, l;
                bsplit2(p0, p1, h, l);
                int off = ch * 18432 + (R + rr * 8) * 144 + cc * 2;
                *(uint32_t*)(smem + off)         = h;
                *(uint32_t*)(smem + 36864 + off) = l;
            }
        }

    // Shuffle-reduce column sums over the 8 lanes sharing a column, then atomic.
    #pragma unroll
    for (int ng = 0; ng < 4; ng++)
        #pragma unroll
        for (int c = 0; c < 2; c++) {
            float v = cs[ng][c];
            v += __shfl_xor_sync(0xFFFFFFFF, v, 4);
            v += __shfl_xor_sync(0xFFFFFFFF, v, 8);
            v += __shfl_xor_sync(0xFFFFFFFF, v, 16);
            if ((lane >> 2) == 0) {
                int col = warp_n * 32 + ng * 8 + 2 * (lane & 3) + c;
                atomicAdd(&g_colsum[b * SEQ + kt * 128 + col], v);
            }
        }
    __syncthreads();

    // Dump the staged blob (coalesced)
    {
        size_t blob = ((size_t)(b * NT + qt) * NT + kt) * TS;
        uint4* d4 = (uint4*)(g_P + blob);
        const uint4* s4 = (const uint4*)smem;
        #pragma unroll
        for (int i = 0; i < 18; i++) d4[tid + i * 256] = s4[tid + i * 256];
    }
}

// ---------------------------------------------------------------------------
// Kernel 2: O += sum_{k in split} P~[q,k] * W~[k,d]  (RED.ADD into d_out)
// Pipelined 32-k sub-chunks, 16 steps (4 kb blocks x 4 subs), occ 2.
// ---------------------------------------------------------------------------
__global__ __launch_bounds__(256, 2)
void out_hmma(float* __restrict__ O) {
    extern __shared__ char smem[];
    uint32_t sb = smem_u32(smem);
    int tid = threadIdx.x, lane = tid & 31, wid = tid >> 5;
    int warp_m = wid >> 2, warp_n = wid & 3;
    int qt = blockIdx.x, split = blockIdx.y, b = blockIdx.z;

    float acc[4][4][4];
    #pragma unroll
    for (int i = 0; i < 4; i++)
        #pragma unroll
        for (int j = 0; j < 4; j++)
            #pragma unroll
            for (int c = 0; c < 4; c++) acc[i][j][c] = 0.f;

    auto issue = [&](int s, int bi) {
        int kb = split * (NT / NS2) + (s >> 2);
        int ch = (s >> 1) & 1, h = s & 1;
        const uint32_t* Pb = g_P + ((size_t)(b * NT + qt) * NT + kb) * TS;
        const uint32_t* Wb = g_W + (size_t)(b * NT + kb) * TS;
        issue_sub(sb + bi * STAGE_BYTES, Pb, Wb, ch, h, tid);
    };

    issue(0, 0);
    issue(1, 1);

    const int NSTEP = 4 * (NT / NS2);   // 16
    for (int s = 0; s < NSTEP; s++) {
        if (s < NSTEP - 1) cp_wait1(); else cp_wait0();
        __syncthreads();
        mma_sub(sb + (s & 1) * STAGE_BYTES, acc, warp_m, warp_n, lane);
        __syncthreads();
        if (s + 2 < NSTEP) issue(s + 2, s & 1);
    }

    // Epilogue: reduce partials straight into the output (RED.ADD.F32)
    float* Ob = O + ((size_t)b * SEQ + qt * 128) * DK;
    #pragma unroll
    for (int mi = 0; mi < 4; mi++)
        #pragma unroll
        for (int ng = 0; ng < 4; ng++) {
            int R = warp_m * 64 + mi * 16 + (lane >> 2);
            int C = warp_n * 32 + ng * 8 + 2 * (lane & 3);
            atomicAdd(&Ob[(size_t)R * DK + C],           acc[mi][ng][0]);
            atomicAdd(&Ob[(size_t)R * DK + C + 1],       acc[mi][ng][1]);
            atomicAdd(&Ob[(size_t)(R + 8) * DK + C],     acc[mi][ng][2]);
            atomicAdd(&Ob[(size_t)(R + 8) * DK + C + 1], acc[mi][ng][3]);
        }
}

// ---------------------------------------------------------------------------
extern "C" void kernel_launch(void* const* d_in, const int* in_sizes, int n_in,
                              void* d_out, int out_size) {
    const float* q = (const float*)d_in[0];
    const float* k = (const float*)d_in[1];
    const float* v = (const float*)d_in[2];
    float* out = (float*)d_out;

    cudaFuncSetAttribute(scores_hmma, cudaFuncAttributeMaxDynamicSharedMemorySize, SMEM_BYTES);
    cudaFuncSetAttribute(out_hmma,    cudaFuncAttributeMaxDynamicSharedMemorySize, SMEM_BYTES);

    zero_kernel<<<(BS * SEQ + 511) / 512, 512>>>();
    zero_out_kernel<<<(BS * SEQ * DK / 4 + 255) / 256, 256>>>(out);
    convert_qk<<<dim3(NT, 2, BS), 256>>>(q, k);
    scores_hmma<<<dim3(NT, NT, BS), 256, SMEM_BYTES>>>();
    recip_kernel<<<(BS * SEQ + 511) / 512, 512>>>();
    convert_v<<<dim3(NT, BS), 256>>>(v);
    out_hmma<<<dim3(NT, NS2, BS), 256, SMEM_BYTES>>>(out);
}